// round 3
// baseline (speedup 1.0000x reference)
#include <cuda_runtime.h>
#include <math.h>

#define BATCH 8
#define NN    2048
#define FIN   256
#define FOUT  256
#define NEG_INF_F (-9000000000000000.0f)
#define ALPHA_F 0.2f

#define BI 64   // i-rows per attention block
#define BJ 32   // j-cols per attention tile

// Scratch (static device globals; no allocation anywhere)
__device__ __align__(16) float g_Wh[BATCH * NN * FOUT];   // 16.8 MB
__device__ float g_f1[BATCH * NN];
__device__ float g_f2[BATCH * NN];

// ---------------------------------------------------------------------------
// Kernel 1: Wh[row][o] = sum_f h[row][f] * W[o][f]   (rows = B*N flattened)
// 64x64 tile, K-step 32, 256 threads, 4x4 micro-tile per thread.
// ---------------------------------------------------------------------------
__global__ void __launch_bounds__(256) gemm_wh_kernel(const float* __restrict__ h,
                                                      const float* __restrict__ W) {
    __shared__ float hs[64][33];
    __shared__ float ws[64][33];

    const int row0 = blockIdx.y * 64;
    const int col0 = blockIdx.x * 64;
    const int tid = threadIdx.x;
    const int tx = tid & 15;   // 16 col groups
    const int ty = tid >> 4;   // 16 row groups

    float acc[4][4] = {};

    for (int k0 = 0; k0 < FIN; k0 += 32) {
        #pragma unroll
        for (int t = 0; t < 8; t++) {
            int idx = tid + t * 256;
            int r = idx >> 5, k = idx & 31;
            hs[r][k] = h[(size_t)(row0 + r) * FIN + k0 + k];
            ws[r][k] = W[(size_t)(col0 + r) * FIN + k0 + k];
        }
        __syncthreads();
        #pragma unroll
        for (int k = 0; k < 32; k++) {
            float av[4], bv[4];
            #pragma unroll
            for (int i = 0; i < 4; i++) av[i] = hs[ty * 4 + i][k];
            #pragma unroll
            for (int j = 0; j < 4; j++) bv[j] = ws[tx * 4 + j][k];
            #pragma unroll
            for (int i = 0; i < 4; i++)
                #pragma unroll
                for (int j = 0; j < 4; j++)
                    acc[i][j] = fmaf(av[i], bv[j], acc[i][j]);
        }
        __syncthreads();
    }

    #pragma unroll
    for (int i = 0; i < 4; i++) {
        float4 v = make_float4(acc[i][0], acc[i][1], acc[i][2], acc[i][3]);
        *(float4*)&g_Wh[(size_t)(row0 + ty * 4 + i) * FOUT + col0 + tx * 4] = v;
    }
}

// ---------------------------------------------------------------------------
// Kernel 2: f1[row] = Wh[row]·a[0:256],  f2[row] = Wh[row]·a[256:512]
// One warp per row.
// ---------------------------------------------------------------------------
__global__ void __launch_bounds__(256) fvec_kernel(const float* __restrict__ a) {
    int gwarp = (blockIdx.x * blockDim.x + threadIdx.x) >> 5;
    int lane = threadIdx.x & 31;
    if (gwarp >= BATCH * NN) return;
    const float* wh = g_Wh + (size_t)gwarp * FOUT;
    float s1 = 0.f, s2 = 0.f;
    #pragma unroll
    for (int k = lane; k < FOUT; k += 32) {
        float v = wh[k];
        s1 = fmaf(v, a[k], s1);
        s2 = fmaf(v, a[FOUT + k], s2);
    }
    #pragma unroll
    for (int o = 16; o > 0; o >>= 1) {
        s1 += __shfl_xor_sync(0xffffffffu, s1, o);
        s2 += __shfl_xor_sync(0xffffffffu, s2, o);
    }
    if (lane == 0) { g_f1[gwarp] = s1; g_f2[gwarp] = s2; }
}

// ---------------------------------------------------------------------------
// Kernel 3: fused masked-softmax attention (flash-attention style).
// Block = 256 threads, BI=64 rows of one batch, j in BJ=32 tiles with online
// softmax. Softmax uses ALL 256 threads: 4 threads per row (JW=8 j's each),
// reductions via shfl in aligned 4-thread groups; lane sc==0 owns (m, l).
// adj is software-pipelined: next tile's 8 values prefetched into registers
// so the DRAM latency overlaps the current tile's FMA phase.
// FMA phase: 4 rows x 16 strided cols per thread (conflict-free LDS).
// ---------------------------------------------------------------------------
#define JW (BJ / 4)   // 8 j's per softmax thread

__global__ void __launch_bounds__(256, 2) attn_kernel(const int* __restrict__ adj,
                                                      float* __restrict__ out) {
    __shared__ float whs[BJ][FOUT];       // 32 KB, row j contiguous
    __shared__ float Ps[BI][BJ + 1];      // probabilities (+1 pad)
    __shared__ float scale_s[BI];
    __shared__ float f2s[BJ];
    __shared__ float inv_l[BI];

    const int b  = blockIdx.y;
    const int i0 = blockIdx.x * BI;
    const int tid = threadIdx.x;

    // FMA-phase mapping
    const int tc = tid & 15;   // 16 col groups; cols = tc + 16*q
    const int tr = tid >> 4;   // 16 row groups; rows = tr*4 + i

    // softmax-phase mapping: 4 threads per row
    const int sr = tid >> 2;          // row 0..63
    const int sc = tid & 3;           // quarter 0..3 -> j = sc*JW .. +JW
    const bool owner = (sc == 0);

    const float* __restrict__ Whb  = g_Wh + (size_t)b * NN * FOUT;
    const int*   __restrict__ adjb = adj  + (size_t)b * NN * NN;

    float acc[4][16];
    #pragma unroll
    for (int i = 0; i < 4; i++)
        #pragma unroll
        for (int q = 0; q < 16; q++) acc[i][q] = 0.f;

    // per-row online-softmax state (held in owner lane sc==0)
    float m_r = -INFINITY, l_r = 0.f;
    const float fi = g_f1[(size_t)b * NN + i0 + sr];   // all 4 lanes keep fi

    // adj prefetch pipeline: this thread's 8 adj entries for the current tile
    const int* arow = adjb + (size_t)(i0 + sr) * NN + sc * JW;
    int4 pa0 = *(const int4*)(arow);
    int4 pa1 = *(const int4*)(arow + 4);

    for (int j0 = 0; j0 < NN; j0 += BJ) {
        __syncthreads();   // previous tile's compute done before overwriting smem

        // --- cooperative loads ---
        {   // Wh tile: rows j0..j0+31 contiguous -> straight float4 copy
            const float4* src = (const float4*)(Whb + (size_t)j0 * FOUT);
            float4* dst = (float4*)&whs[0][0];
            #pragma unroll
            for (int t = 0; t < 8; t++) dst[tid + t * 256] = src[tid + t * 256];
        }
        if (tid < BJ) f2s[tid] = g_f2[(size_t)b * NN + j0 + tid];
        __syncthreads();

        // --- softmax phase: 4 threads per row, e kept in registers ---
        int am[JW] = {pa0.x, pa0.y, pa0.z, pa0.w, pa1.x, pa1.y, pa1.z, pa1.w};

        // prefetch next tile's adj now; latency overlaps exp + FMA phases
        if (j0 + BJ < NN) {
            pa0 = *(const int4*)(arow + (j0 + BJ));
            pa1 = *(const int4*)(arow + (j0 + BJ) + 4);
        }

        float ev[JW];
        float mloc = -INFINITY;
        #pragma unroll
        for (int j = 0; j < JW; j++) {
            float e = fi + f2s[sc * JW + j];
            e = (e > 0.f) ? e : ALPHA_F * e;
            e = (am[j] == 0) ? NEG_INF_F : e;
            ev[j] = e;
            mloc = fmaxf(mloc, e);
        }
        // row-max across the aligned 4-thread group
        mloc = fmaxf(mloc, __shfl_xor_sync(0xffffffffu, mloc, 1));
        mloc = fmaxf(mloc, __shfl_xor_sync(0xffffffffu, mloc, 2));

        // owner updates m; broadcast m_new & scale from lane (tid & ~3)
        float m_new, scale;
        if (owner) {
            m_new = fmaxf(m_r, mloc);          // finite (>= NEG_INF_F)
            scale = __expf(m_r - m_new);       // 0 on first tile (m_r=-inf)
            m_r = m_new;
        }
        m_new = __shfl_sync(0xffffffffu, m_new, (tid & 31) & ~3);
        scale = __shfl_sync(0xffffffffu, scale, (tid & 31) & ~3);

        float sum = 0.f;
        #pragma unroll
        for (int j = 0; j < JW; j++) {
            float p = __expf(ev[j] - m_new);   // underflows to 0 when masked
            Ps[sr][sc * JW + j] = p;
            sum += p;
        }
        sum += __shfl_xor_sync(0xffffffffu, sum, 1);
        sum += __shfl_xor_sync(0xffffffffu, sum, 2);
        if (owner) {
            l_r = l_r * scale + sum;
            scale_s[sr] = scale;
        }
        __syncthreads();

        // --- rescale accumulators + P @ Wh_tile ---
        #pragma unroll
        for (int i = 0; i < 4; i++) {
            float s = scale_s[tr * 4 + i];
            #pragma unroll
            for (int q = 0; q < 16; q++) acc[i][q] *= s;
        }
        #pragma unroll 4
        for (int j = 0; j < BJ; j++) {
            float p0 = Ps[tr * 4 + 0][j];
            float p1 = Ps[tr * 4 + 1][j];
            float p2 = Ps[tr * 4 + 2][j];
            float p3 = Ps[tr * 4 + 3][j];
            #pragma unroll
            for (int q = 0; q < 16; q++) {
                float w = whs[j][tc + (q << 4)];
                acc[0][q] = fmaf(p0, w, acc[0][q]);
                acc[1][q] = fmaf(p1, w, acc[1][q]);
                acc[2][q] = fmaf(p2, w, acc[2][q]);
                acc[3][q] = fmaf(p3, w, acc[3][q]);
            }
        }
    }

    if (owner) inv_l[sr] = 1.0f / l_r;
    __syncthreads();

    float* outb = out + (size_t)b * NN * FOUT;
    #pragma unroll
    for (int i = 0; i < 4; i++) {
        int r = tr * 4 + i;
        float il = inv_l[r];
        #pragma unroll
        for (int q = 0; q < 16; q++) {
            outb[(size_t)(i0 + r) * FOUT + tc + (q << 4)] = acc[i][q] * il;
        }
    }
}

// ---------------------------------------------------------------------------
extern "C" void kernel_launch(void* const* d_in, const int* in_sizes, int n_in,
                              void* d_out, int out_size) {
    (void)in_sizes; (void)n_in; (void)out_size;
    const float* h   = (const float*)d_in[0];
    const int*   adj = (const int*)d_in[1];
    const float* W   = (const float*)d_in[2];
    const float* a   = (const float*)d_in[3];
    float* out = (float*)d_out;

    dim3 g1(FOUT / 64, (BATCH * NN) / 64);       // (4, 256)
    gemm_wh_kernel<<<g1, 256>>>(h, W);

    fvec_kernel<<<(BATCH * NN * 32) / 256, 256>>>(a);  // one warp per row

    dim3 g3(NN / BI, BATCH);                     // (32, 8)
    attn_kernel<<<g3, 256>>>(adj, out);
}

// round 9
// speedup vs baseline: 1.6832x; 1.6832x over previous
#include <cuda_runtime.h>
#include <cuda_bf16.h>
#include <math.h>
#include <stdint.h>

#define BATCH 8
#define NN    2048
#define FIN   256
#define FOUT  256
#define NEG_INF_F (-9000000000000000.0f)
#define ALPHA_F 0.2f

#define BI 64             // i-rows per attention block
#define BJ 32             // j-cols per tile (MMA K per tile; 2 x k=16 chunks)
#define NT (NN / BJ)      // 64 tiles
#define KPAD 40           // padded k-stride (elements) for smem tiles (80 B, 16B-mult)

// Scratch (static device globals; no allocation anywhere)
__device__ __align__(16) float g_Wh[BATCH * NN * FOUT];            // 16.8 MB
__device__ __align__(16) __nv_bfloat16 g_WhhT[BATCH * FOUT * NN];  // [b][n][j] hi
__device__ __align__(16) __nv_bfloat16 g_WhlT[BATCH * FOUT * NN];  // [b][n][j] lo
__device__ float g_f1[BATCH * NN];
__device__ float g_f2[BATCH * NN];

// ---------------------------------------------------------------------------
// Helpers: ldmatrix + mma.sync (sm_80-class PTX; valid at compute_103)
// ---------------------------------------------------------------------------
__device__ __forceinline__ uint32_t smem_u32(const void* p) {
    uint32_t a;
    asm("{ .reg .u64 t; cvta.to.shared.u64 t, %1; cvt.u32.u64 %0, t; }" : "=r"(a) : "l"(p));
    return a;
}
__device__ __forceinline__ void ldsm4(uint32_t& r0, uint32_t& r1, uint32_t& r2, uint32_t& r3,
                                      uint32_t addr) {
    asm volatile("ldmatrix.sync.aligned.m8n8.x4.shared.b16 {%0,%1,%2,%3}, [%4];"
                 : "=r"(r0), "=r"(r1), "=r"(r2), "=r"(r3) : "r"(addr));
}
__device__ __forceinline__ void mma16816(float* c, uint32_t a0, uint32_t a1, uint32_t a2,
                                         uint32_t a3, uint32_t b0, uint32_t b1) {
    asm volatile(
        "mma.sync.aligned.m16n8k16.row.col.f32.bf16.bf16.f32 "
        "{%0,%1,%2,%3}, {%4,%5,%6,%7}, {%8,%9}, {%0,%1,%2,%3};"
        : "+f"(c[0]), "+f"(c[1]), "+f"(c[2]), "+f"(c[3])
        : "r"(a0), "r"(a1), "r"(a2), "r"(a3), "r"(b0), "r"(b1));
}

// ---------------------------------------------------------------------------
// Kernel 1: Wh[row][o] = sum_f h[row][f] * W[o][f]  (unchanged; 68.7us, passes)
// ---------------------------------------------------------------------------
__global__ void __launch_bounds__(256) gemm_wh_kernel(const float* __restrict__ h,
                                                      const float* __restrict__ W) {
    __shared__ float hs[64][33];
    __shared__ float ws[64][33];

    const int row0 = blockIdx.y * 64;
    const int col0 = blockIdx.x * 64;
    const int tid = threadIdx.x;
    const int tx = tid & 15;
    const int ty = tid >> 4;

    float acc[4][4] = {};

    for (int k0 = 0; k0 < FIN; k0 += 32) {
        #pragma unroll
        for (int t = 0; t < 8; t++) {
            int idx = tid + t * 256;
            int r = idx >> 5, k = idx & 31;
            hs[r][k] = h[(size_t)(row0 + r) * FIN + k0 + k];
            ws[r][k] = W[(size_t)(col0 + r) * FIN + k0 + k];
        }
        __syncthreads();
        #pragma unroll
        for (int k = 0; k < 32; k++) {
            float av[4], bv[4];
            #pragma unroll
            for (int i = 0; i < 4; i++) av[i] = hs[ty * 4 + i][k];
            #pragma unroll
            for (int j = 0; j < 4; j++) bv[j] = ws[tx * 4 + j][k];
            #pragma unroll
            for (int i = 0; i < 4; i++)
                #pragma unroll
                for (int j = 0; j < 4; j++)
                    acc[i][j] = fmaf(av[i], bv[j], acc[i][j]);
        }
        __syncthreads();
    }

    #pragma unroll
    for (int i = 0; i < 4; i++) {
        float4 v = make_float4(acc[i][0], acc[i][1], acc[i][2], acc[i][3]);
        *(float4*)&g_Wh[(size_t)(row0 + ty * 4 + i) * FOUT + col0 + tx * 4] = v;
    }
}

// ---------------------------------------------------------------------------
// Kernel 1b: transpose + bf16 hi/lo split: g_Wh[b][j][n] -> g_WhhT/g_WhlT[b][n][j]
// 64x64 tiles through smem; coalesced on both sides.
// ---------------------------------------------------------------------------
__global__ void __launch_bounds__(256) transp_kernel() {
    __shared__ float ts[64][65];
    const int b  = blockIdx.z;
    const int j0 = blockIdx.x * 64;
    const int n0 = blockIdx.y * 64;
    const int tid = threadIdx.x;

    #pragma unroll
    for (int it = 0; it < 16; it++) {
        int idx = tid + it * 256;
        int r = idx >> 6, c = idx & 63;
        ts[r][c] = g_Wh[((size_t)b * NN + j0 + r) * FOUT + n0 + c];
    }
    __syncthreads();

    const int tx = tid & 31;   // j-pair index (32 pairs of j)
    const int ty = tid >> 5;   // n base (8 per iter)
    #pragma unroll
    for (int it = 0; it < 8; it++) {
        int n = ty + it * 8;
        float w0 = ts[tx * 2 + 0][n];
        float w1 = ts[tx * 2 + 1][n];
        __nv_bfloat16 h0 = __float2bfloat16(w0);
        __nv_bfloat16 h1 = __float2bfloat16(w1);
        __nv_bfloat16 l0 = __float2bfloat16(w0 - __bfloat162float(h0));
        __nv_bfloat16 l1 = __float2bfloat16(w1 - __bfloat162float(h1));
        size_t off = ((size_t)b * FOUT + n0 + n) * NN + j0 + tx * 2;
        __nv_bfloat162 vh; vh.x = h0; vh.y = h1;
        __nv_bfloat162 vl; vl.x = l0; vl.y = l1;
        *(__nv_bfloat162*)&g_WhhT[off] = vh;
        *(__nv_bfloat162*)&g_WhlT[off] = vl;
    }
}

// ---------------------------------------------------------------------------
// Kernel 2: f1/f2 (unchanged)
// ---------------------------------------------------------------------------
__global__ void __launch_bounds__(256) fvec_kernel(const float* __restrict__ a) {
    int gwarp = (blockIdx.x * blockDim.x + threadIdx.x) >> 5;
    int lane = threadIdx.x & 31;
    if (gwarp >= BATCH * NN) return;
    const float* wh = g_Wh + (size_t)gwarp * FOUT;
    float s1 = 0.f, s2 = 0.f;
    #pragma unroll
    for (int k = lane; k < FOUT; k += 32) {
        float v = wh[k];
        s1 = fmaf(v, a[k], s1);
        s2 = fmaf(v, a[FOUT + k], s2);
    }
    #pragma unroll
    for (int o = 16; o > 0; o >>= 1) {
        s1 += __shfl_xor_sync(0xffffffffu, s1, o);
        s2 += __shfl_xor_sync(0xffffffffu, s2, o);
    }
    if (lane == 0) { g_f1[gwarp] = s1; g_f2[gwarp] = s2; }
}

// ---------------------------------------------------------------------------
// Kernel 3: warp-MMA fused attention (mma.sync m16n8k16 bf16, fp32 accum).
// Block: 64 rows x 256 cols; 8 warps as 4(M) x 2(N); each warp 16x128 output.
// Per j-tile (32): P exp'd + hi/lo split to smem; Wh tile copied from
// pre-split g_WhhT/g_WhlT. 3-term split MMA: Ah*Bh + Ah*Bl + Al*Bh.
// No online softmax (|e| <= ~6): unnormalized accumulate, divide by l at end.
// 2 CTAs/SM provide convert/MMA overlap.
//
// smem (51456 B dynamic):
//   BS_HI 0      (256 x KPAD bf16 = 20480)
//   BS_LO 20480
//   PS_HI 40960  (64 x KPAD bf16 = 5120)
//   PS_LO 46080
//   LS    51200  (64 f)
// ---------------------------------------------------------------------------
#define BS_HI 0u
#define BS_LO 20480u
#define PS_HI 40960u
#define PS_LO 46080u
#define LS    51200u
#define ATTN_SMEM 51456

__global__ void __launch_bounds__(256, 2) attn_mma_kernel(const int* __restrict__ adj,
                                                          float* __restrict__ out) {
    extern __shared__ char smem[];
    const uint32_t sbase = smem_u32(smem);

    const int tid  = threadIdx.x;
    const int warp = tid >> 5;
    const int lane = tid & 31;
    const int b  = blockIdx.y;
    const int i0 = blockIdx.x * BI;

    const int wm = warp & 3;   // M block (16 rows)
    const int wn = warp >> 2;  // N block (128 cols)

    // softmax mapping: 4 threads per row, 8 j each
    const int sr = tid >> 2;
    const int sc = tid & 3;
    const float fi = g_f1[(size_t)b * NN + i0 + sr];
    const int* arow = adj + (size_t)b * NN * NN + (size_t)(i0 + sr) * NN + sc * 8;

    int4 pa0 = *(const int4*)(arow);
    int4 pa1 = *(const int4*)(arow + 4);

    float acc[8][8];
    #pragma unroll
    for (int i = 0; i < 8; i++)
        #pragma unroll
        for (int j = 0; j < 8; j++) acc[i][j] = 0.f;

    float lpart = 0.f;

    // precomputed smem addresses
    const uint32_t aAhiBase = sbase + PS_HI +
        2u * (uint32_t)((wm * 16 + (lane & 15)) * KPAD + ((lane >> 4) << 3));
    const uint32_t aAloBase = aAhiBase + (PS_LO - PS_HI);

    for (int t = 0; t < NT; t++) {
        const int j0 = t * BJ;
        __syncthreads();   // previous tile's MMA done before overwriting smem

        // --- Wh tile copy: row n = tid, 32 bf16 hi + lo (pre-split global) ---
        {
            const uint4* sH = (const uint4*)(g_WhhT + ((size_t)(b * FOUT + tid)) * NN + j0);
            const uint4* sL = (const uint4*)(g_WhlT + ((size_t)(b * FOUT + tid)) * NN + j0);
            uint4* dH = (uint4*)(smem + BS_HI + (uint32_t)tid * (2 * KPAD));
            uint4* dL = (uint4*)(smem + BS_LO + (uint32_t)tid * (2 * KPAD));
            #pragma unroll
            for (int k = 0; k < 4; k++) { dH[k] = sH[k]; dL[k] = sL[k]; }
        }

        // --- P tile: e -> exp -> bf16 hi/lo split (8 j per thread) ---
        {
            float4 f2a = *(const float4*)(g_f2 + (size_t)b * NN + j0 + sc * 8);
            float4 f2b = *(const float4*)(g_f2 + (size_t)b * NN + j0 + sc * 8 + 4);
            float f2v[8] = {f2a.x, f2a.y, f2a.z, f2a.w, f2b.x, f2b.y, f2b.z, f2b.w};
            int   am[8]  = {pa0.x, pa0.y, pa0.z, pa0.w, pa1.x, pa1.y, pa1.z, pa1.w};
            float pv[8];
            #pragma unroll
            for (int q = 0; q < 8; q++) {
                float e = fi + f2v[q];
                e = (e > 0.f) ? e : ALPHA_F * e;
                e = (am[q] == 0) ? NEG_INF_F : e;
                float p = __expf(e);       // 0 when masked; |e|<=~6 otherwise
                lpart += p;
                pv[q] = p;
            }
            union { __nv_bfloat162 h2[4]; uint4 u; } ph, pl;
            #pragma unroll
            for (int q = 0; q < 4; q++) {
                __nv_bfloat16 h0 = __float2bfloat16(pv[2 * q]);
                __nv_bfloat16 h1 = __float2bfloat16(pv[2 * q + 1]);
                ph.h2[q].x = h0; ph.h2[q].y = h1;
                pl.h2[q].x = __float2bfloat16(pv[2 * q] - __bfloat162float(h0));
                pl.h2[q].y = __float2bfloat16(pv[2 * q + 1] - __bfloat162float(h1));
            }
            uint32_t po = (uint32_t)(sr * (2 * KPAD) + sc * 16);
            *(uint4*)(smem + PS_HI + po) = ph.u;
            *(uint4*)(smem + PS_LO + po) = pl.u;
        }

        // prefetch next tile's adj (latency hidden by MMA phase)
        if (t + 1 < NT) {
            pa0 = *(const int4*)(arow + (j0 + BJ));
            pa1 = *(const int4*)(arow + (j0 + BJ) + 4);
        }
        __syncthreads();

        // --- MMA phase: 2 k-chunks x 8 n-pairs x 6 mma ---
        #pragma unroll
        for (int kc = 0; kc < 2; kc++) {
            uint32_t ah0, ah1, ah2, ah3, al0, al1, al2, al3;
            ldsm4(ah0, ah1, ah2, ah3, aAhiBase + (uint32_t)(kc * 32));
            ldsm4(al0, al1, al2, al3, aAloBase + (uint32_t)(kc * 32));

            const int nbase = wn * 128 + (lane & 7) + ((lane >> 4) << 3);
            const int kcol  = kc * 16 + (((lane >> 3) & 1) << 3);
            #pragma unroll
            for (int np = 0; np < 8; np++) {
                uint32_t boff = 2u * (uint32_t)((nbase + np * 16) * KPAD + kcol);
                uint32_t bh0, bh1, bh2, bh3, bl0, bl1, bl2, bl3;
                ldsm4(bh0, bh1, bh2, bh3, sbase + BS_HI + boff);
                ldsm4(bl0, bl1, bl2, bl3, sbase + BS_LO + boff);
                mma16816(acc[np] + 0, ah0, ah1, ah2, ah3, bh0, bh1);
                mma16816(acc[np] + 0, ah0, ah1, ah2, ah3, bl0, bl1);
                mma16816(acc[np] + 0, al0, al1, al2, al3, bh0, bh1);
                mma16816(acc[np] + 4, ah0, ah1, ah2, ah3, bh2, bh3);
                mma16816(acc[np] + 4, ah0, ah1, ah2, ah3, bl2, bl3);
                mma16816(acc[np] + 4, al0, al1, al2, al3, bh2, bh3);
            }
        }
    }

    // --- l reduction across the 4-thread row group (consecutive lanes) ---
    float ls = lpart;
    ls += __shfl_xor_sync(0xffffffffu, ls, 1);
    ls += __shfl_xor_sync(0xffffffffu, ls, 2);
    float* l_s = (float*)(smem + LS);
    if (sc == 0) l_s[sr] = ls;
    __syncthreads();

    // --- normalize + write (fp32, 8B stores; 32B contiguous per 4 lanes) ---
    const int r0 = wm * 16 + (lane >> 2);
    const int r1 = r0 + 8;
    const float inv0 = 1.0f / l_s[r0];
    const float inv1 = 1.0f / l_s[r1];
    float* outb = out + ((size_t)b * NN + i0) * FOUT;
    #pragma unroll
    for (int np = 0; np < 8; np++) {
        int c = wn * 128 + np * 16 + (lane & 3) * 2;
        *(float2*)&outb[(size_t)r0 * FOUT + c]     = make_float2(acc[np][0] * inv0, acc[np][1] * inv0);
        *(float2*)&outb[(size_t)r1 * FOUT + c]     = make_float2(acc[np][2] * inv1, acc[np][3] * inv1);
        *(float2*)&outb[(size_t)r0 * FOUT + c + 8] = make_float2(acc[np][4] * inv0, acc[np][5] * inv0);
        *(float2*)&outb[(size_t)r1 * FOUT + c + 8] = make_float2(acc[np][6] * inv1, acc[np][7] * inv1);
    }
}

// ---------------------------------------------------------------------------
extern "C" void kernel_launch(void* const* d_in, const int* in_sizes, int n_in,
                              void* d_out, int out_size) {
    (void)in_sizes; (void)n_in; (void)out_size;
    const float* h   = (const float*)d_in[0];
    const int*   adj = (const int*)d_in[1];
    const float* W   = (const float*)d_in[2];
    const float* a   = (const float*)d_in[3];
    float* out = (float*)d_out;

    cudaFuncSetAttribute(attn_mma_kernel,
                         cudaFuncAttributeMaxDynamicSharedMemorySize, ATTN_SMEM);

    dim3 g1(FOUT / 64, (BATCH * NN) / 64);       // (4, 256)
    gemm_wh_kernel<<<g1, 256>>>(h, W);

    dim3 gt(NN / 64, FOUT / 64, BATCH);          // (32, 4, 8)
    transp_kernel<<<gt, 256>>>();

    fvec_kernel<<<(BATCH * NN * 32) / 256, 256>>>(a);  // one warp per row

    dim3 g3(NN / BI, BATCH);                     // (32, 8)
    attn_mma_kernel<<<g3, 256, ATTN_SMEM>>>(adj, out);
}

// round 11
// speedup vs baseline: 1.8318x; 1.0883x over previous
#include <cuda_runtime.h>
#include <cuda_bf16.h>
#include <math.h>
#include <stdint.h>

#define BATCH 8
#define NN    2048
#define FIN   256
#define FOUT  256
#define NEG_INF_F (-9000000000000000.0f)
#define ALPHA_F 0.2f

#define BI 64             // i-rows per attention block
#define BJ 32             // j-cols per tile (MMA K per tile; 2 x k=16 chunks)
#define NT (NN / BJ)      // 64 tiles
#define KPAD 40           // padded k-stride (elements) for smem tiles (80 B, 16B-mult)

// Scratch (static device globals; no allocation anywhere)
__device__ __align__(16) float g_Wh[BATCH * NN * FOUT];            // 16.8 MB
__device__ __align__(16) __nv_bfloat16 g_WhhT[BATCH * FOUT * NN];  // [b][n][j] hi
__device__ __align__(16) __nv_bfloat16 g_WhlT[BATCH * FOUT * NN];  // [b][n][j] lo
__device__ float g_f1[BATCH * NN];
__device__ float g_f2[BATCH * NN];

// ---------------------------------------------------------------------------
// Helpers: ldmatrix + mma.sync (sm_80-class PTX; valid at compute_103)
// ---------------------------------------------------------------------------
__device__ __forceinline__ uint32_t smem_u32(const void* p) {
    uint32_t a;
    asm("{ .reg .u64 t; cvta.to.shared.u64 t, %1; cvt.u32.u64 %0, t; }" : "=r"(a) : "l"(p));
    return a;
}
__device__ __forceinline__ void ldsm4(uint32_t& r0, uint32_t& r1, uint32_t& r2, uint32_t& r3,
                                      uint32_t addr) {
    asm volatile("ldmatrix.sync.aligned.m8n8.x4.shared.b16 {%0,%1,%2,%3}, [%4];"
                 : "=r"(r0), "=r"(r1), "=r"(r2), "=r"(r3) : "r"(addr));
}
__device__ __forceinline__ void mma16816(float* c, uint32_t a0, uint32_t a1, uint32_t a2,
                                         uint32_t a3, uint32_t b0, uint32_t b1) {
    asm volatile(
        "mma.sync.aligned.m16n8k16.row.col.f32.bf16.bf16.f32 "
        "{%0,%1,%2,%3}, {%4,%5,%6,%7}, {%8,%9}, {%0,%1,%2,%3};"
        : "+f"(c[0]), "+f"(c[1]), "+f"(c[2]), "+f"(c[3])
        : "r"(a0), "r"(a1), "r"(a2), "r"(a3), "r"(b0), "r"(b1));
}

// ---------------------------------------------------------------------------
// Kernel 1: Wh[row][o] = sum_f h[row][f] * W[o][f]  (unchanged; 68.7us, passes)
// ---------------------------------------------------------------------------
__global__ void __launch_bounds__(256) gemm_wh_kernel(const float* __restrict__ h,
                                                      const float* __restrict__ W) {
    __shared__ float hs[64][33];
    __shared__ float ws[64][33];

    const int row0 = blockIdx.y * 64;
    const int col0 = blockIdx.x * 64;
    const int tid = threadIdx.x;
    const int tx = tid & 15;
    const int ty = tid >> 4;

    float acc[4][4] = {};

    for (int k0 = 0; k0 < FIN; k0 += 32) {
        #pragma unroll
        for (int t = 0; t < 8; t++) {
            int idx = tid + t * 256;
            int r = idx >> 5, k = idx & 31;
            hs[r][k] = h[(size_t)(row0 + r) * FIN + k0 + k];
            ws[r][k] = W[(size_t)(col0 + r) * FIN + k0 + k];
        }
        __syncthreads();
        #pragma unroll
        for (int k = 0; k < 32; k++) {
            float av[4], bv[4];
            #pragma unroll
            for (int i = 0; i < 4; i++) av[i] = hs[ty * 4 + i][k];
            #pragma unroll
            for (int j = 0; j < 4; j++) bv[j] = ws[tx * 4 + j][k];
            #pragma unroll
            for (int i = 0; i < 4; i++)
                #pragma unroll
                for (int j = 0; j < 4; j++)
                    acc[i][j] = fmaf(av[i], bv[j], acc[i][j]);
        }
        __syncthreads();
    }

    #pragma unroll
    for (int i = 0; i < 4; i++) {
        float4 v = make_float4(acc[i][0], acc[i][1], acc[i][2], acc[i][3]);
        *(float4*)&g_Wh[(size_t)(row0 + ty * 4 + i) * FOUT + col0 + tx * 4] = v;
    }
}

// ---------------------------------------------------------------------------
// Kernel 1b: transpose + bf16 hi/lo split: g_Wh[b][j][n] -> g_WhhT/g_WhlT[b][n][j]
// ---------------------------------------------------------------------------
__global__ void __launch_bounds__(256) transp_kernel() {
    __shared__ float ts[64][65];
    const int b  = blockIdx.z;
    const int j0 = blockIdx.x * 64;
    const int n0 = blockIdx.y * 64;
    const int tid = threadIdx.x;

    #pragma unroll
    for (int it = 0; it < 16; it++) {
        int idx = tid + it * 256;
        int r = idx >> 6, c = idx & 63;
        ts[r][c] = g_Wh[((size_t)b * NN + j0 + r) * FOUT + n0 + c];
    }
    __syncthreads();

    const int tx = tid & 31;   // j-pair index (32 pairs of j)
    const int ty = tid >> 5;   // n base (8 per iter)
    #pragma unroll
    for (int it = 0; it < 8; it++) {
        int n = ty + it * 8;
        float w0 = ts[tx * 2 + 0][n];
        float w1 = ts[tx * 2 + 1][n];
        __nv_bfloat16 h0 = __float2bfloat16(w0);
        __nv_bfloat16 h1 = __float2bfloat16(w1);
        __nv_bfloat16 l0 = __float2bfloat16(w0 - __bfloat162float(h0));
        __nv_bfloat16 l1 = __float2bfloat16(w1 - __bfloat162float(h1));
        size_t off = ((size_t)b * FOUT + n0 + n) * NN + j0 + tx * 2;
        __nv_bfloat162 vh; vh.x = h0; vh.y = h1;
        __nv_bfloat162 vl; vl.x = l0; vl.y = l1;
        *(__nv_bfloat162*)&g_WhhT[off] = vh;
        *(__nv_bfloat162*)&g_WhlT[off] = vl;
    }
}

// ---------------------------------------------------------------------------
// Kernel 2: f1/f2 (unchanged)
// ---------------------------------------------------------------------------
__global__ void __launch_bounds__(256) fvec_kernel(const float* __restrict__ a) {
    int gwarp = (blockIdx.x * blockDim.x + threadIdx.x) >> 5;
    int lane = threadIdx.x & 31;
    if (gwarp >= BATCH * NN) return;
    const float* wh = g_Wh + (size_t)gwarp * FOUT;
    float s1 = 0.f, s2 = 0.f;
    #pragma unroll
    for (int k = lane; k < FOUT; k += 32) {
        float v = wh[k];
        s1 = fmaf(v, a[k], s1);
        s2 = fmaf(v, a[FOUT + k], s2);
    }
    #pragma unroll
    for (int o = 16; o > 0; o >>= 1) {
        s1 += __shfl_xor_sync(0xffffffffu, s1, o);
        s2 += __shfl_xor_sync(0xffffffffu, s2, o);
    }
    if (lane == 0) { g_f1[gwarp] = s1; g_f2[gwarp] = s2; }
}

// ---------------------------------------------------------------------------
// Kernel 3: warp-MMA fused attention (mma.sync m16n8k16 bf16, fp32 accum).
// RETILED: 8 warps as 2(M) x 4(N); each warp 32 rows x 64 cols.
// Cuts per-tile smem fragment traffic 144KB -> 96KB (A re-read by 4 wn
// groups, B re-read by only 2 wm groups) and LDSM:MMA from 36:96 to 24:96.
// 3-term split MMA: Ah*Bh + Ah*Bl + Al*Bh. Unnormalized accumulate
// (|e| <= ~6 so exp never overflows), divide by l at end. 2 CTAs/SM overlap.
//
// smem (51456 B dynamic):
//   BS_HI 0      (256 x KPAD bf16 = 20480)
//   BS_LO 20480
//   PS_HI 40960  (64 x KPAD bf16 = 5120)
//   PS_LO 46080
//   LS    51200  (64 f)
// ---------------------------------------------------------------------------
#define BS_HI 0u
#define BS_LO 20480u
#define PS_HI 40960u
#define PS_LO 46080u
#define LS    51200u
#define ATTN_SMEM 51456

__global__ void __launch_bounds__(256, 2) attn_mma_kernel(const int* __restrict__ adj,
                                                          float* __restrict__ out) {
    extern __shared__ char smem[];
    const uint32_t sbase = smem_u32(smem);

    const int tid  = threadIdx.x;
    const int warp = tid >> 5;
    const int lane = tid & 31;
    const int b  = blockIdx.y;
    const int i0 = blockIdx.x * BI;

    const int wm = warp & 1;   // M block (32 rows)
    const int wn = warp >> 1;  // N block (64 cols)

    // softmax mapping: 4 threads per row, 8 j each
    const int sr = tid >> 2;
    const int sc = tid & 3;
    const float fi = g_f1[(size_t)b * NN + i0 + sr];
    const int* arow = adj + (size_t)b * NN * NN + (size_t)(i0 + sr) * NN + sc * 8;

    int4 pa0 = *(const int4*)(arow);
    int4 pa1 = *(const int4*)(arow + 4);

    // acc[mt][np][8]: mt = m16 tile (2), np = n16 pair (4), 8 floats each
    float acc[2][4][8];
    #pragma unroll
    for (int i = 0; i < 2; i++)
        #pragma unroll
        for (int j = 0; j < 4; j++)
            #pragma unroll
            for (int k = 0; k < 8; k++) acc[i][j][k] = 0.f;

    float lpart = 0.f;

    // A (P) ldsm base: rows wm*32 + mt*16 + (lane&15), col (lane>>4)*8
    const uint32_t aAhiBase = sbase + PS_HI +
        2u * (uint32_t)((wm * 32 + (lane & 15)) * KPAD + ((lane >> 4) << 3));
    const uint32_t aAloBase = aAhiBase + (PS_LO - PS_HI);

    for (int t = 0; t < NT; t++) {
        const int j0 = t * BJ;
        __syncthreads();   // previous tile's MMA done before overwriting smem

        // --- Wh tile copy: row n = tid, 32 bf16 hi + lo (pre-split global) ---
        {
            const uint4* sH = (const uint4*)(g_WhhT + ((size_t)(b * FOUT + tid)) * NN + j0);
            const uint4* sL = (const uint4*)(g_WhlT + ((size_t)(b * FOUT + tid)) * NN + j0);
            uint4* dH = (uint4*)(smem + BS_HI + (uint32_t)tid * (2 * KPAD));
            uint4* dL = (uint4*)(smem + BS_LO + (uint32_t)tid * (2 * KPAD));
            #pragma unroll
            for (int k = 0; k < 4; k++) { dH[k] = sH[k]; dL[k] = sL[k]; }
        }

        // --- P tile: e -> exp -> bf16 hi/lo split (8 j per thread) ---
        {
            float4 f2a = *(const float4*)(g_f2 + (size_t)b * NN + j0 + sc * 8);
            float4 f2b = *(const float4*)(g_f2 + (size_t)b * NN + j0 + sc * 8 + 4);
            float f2v[8] = {f2a.x, f2a.y, f2a.z, f2a.w, f2b.x, f2b.y, f2b.z, f2b.w};
            int   am[8]  = {pa0.x, pa0.y, pa0.z, pa0.w, pa1.x, pa1.y, pa1.z, pa1.w};
            float pv[8];
            #pragma unroll
            for (int q = 0; q < 8; q++) {
                float e = fi + f2v[q];
                e = (e > 0.f) ? e : ALPHA_F * e;
                e = (am[q] == 0) ? NEG_INF_F : e;
                float p = __expf(e);       // 0 when masked; |e|<=~6 otherwise
                lpart += p;
                pv[q] = p;
            }
            union { __nv_bfloat162 h2[4]; uint4 u; } ph, pl;
            #pragma unroll
            for (int q = 0; q < 4; q++) {
                __nv_bfloat16 h0 = __float2bfloat16(pv[2 * q]);
                __nv_bfloat16 h1 = __float2bfloat16(pv[2 * q + 1]);
                ph.h2[q].x = h0; ph.h2[q].y = h1;
                pl.h2[q].x = __float2bfloat16(pv[2 * q] - __bfloat162float(h0));
                pl.h2[q].y = __float2bfloat16(pv[2 * q + 1] - __bfloat162float(h1));
            }
            uint32_t po = (uint32_t)(sr * (2 * KPAD) + sc * 16);
            *(uint4*)(smem + PS_HI + po) = ph.u;
            *(uint4*)(smem + PS_LO + po) = pl.u;
        }

        // prefetch next tile's adj (latency hidden by MMA phase)
        if (t + 1 < NT) {
            pa0 = *(const int4*)(arow + (j0 + BJ));
            pa1 = *(const int4*)(arow + (j0 + BJ) + 4);
        }
        __syncthreads();

        // --- MMA phase: 2 k-chunks x (2 mt A-ldsm + 4 np B-ldsm) x mma ---
        #pragma unroll
        for (int kc = 0; kc < 2; kc++) {
            uint32_t ah[2][4], al[2][4];
            #pragma unroll
            for (int mt = 0; mt < 2; mt++) {
                ldsm4(ah[mt][0], ah[mt][1], ah[mt][2], ah[mt][3],
                      aAhiBase + (uint32_t)(mt * 16 * KPAD * 2 + kc * 32));
                ldsm4(al[mt][0], al[mt][1], al[mt][2], al[mt][3],
                      aAloBase + (uint32_t)(mt * 16 * KPAD * 2 + kc * 32));
            }

            const int nbase = wn * 64 + (lane & 7) + ((lane >> 4) << 3);
            const int kcol  = kc * 16 + (((lane >> 3) & 1) << 3);
            #pragma unroll
            for (int np = 0; np < 4; np++) {
                uint32_t boff = 2u * (uint32_t)((nbase + np * 16) * KPAD + kcol);
                uint32_t bh0, bh1, bh2, bh3, bl0, bl1, bl2, bl3;
                ldsm4(bh0, bh1, bh2, bh3, sbase + BS_HI + boff);
                ldsm4(bl0, bl1, bl2, bl3, sbase + BS_LO + boff);
                #pragma unroll
                for (int mt = 0; mt < 2; mt++) {
                    mma16816(acc[mt][np] + 0, ah[mt][0], ah[mt][1], ah[mt][2], ah[mt][3], bh0, bh1);
                    mma16816(acc[mt][np] + 0, ah[mt][0], ah[mt][1], ah[mt][2], ah[mt][3], bl0, bl1);
                    mma16816(acc[mt][np] + 0, al[mt][0], al[mt][1], al[mt][2], al[mt][3], bh0, bh1);
                    mma16816(acc[mt][np] + 4, ah[mt][0], ah[mt][1], ah[mt][2], ah[mt][3], bh2, bh3);
                    mma16816(acc[mt][np] + 4, ah[mt][0], ah[mt][1], ah[mt][2], ah[mt][3], bl2, bl3);
                    mma16816(acc[mt][np] + 4, al[mt][0], al[mt][1], al[mt][2], al[mt][3], bh2, bh3);
                }
            }
        }
    }

    // --- l reduction across the 4-thread row group (consecutive lanes) ---
    float ls = lpart;
    ls += __shfl_xor_sync(0xffffffffu, ls, 1);
    ls += __shfl_xor_sync(0xffffffffu, ls, 2);
    float* l_s = (float*)(smem + LS);
    if (sc == 0) l_s[sr] = ls;
    __syncthreads();

    // --- normalize + write (fp32, 8B stores; 32B contiguous per 4 lanes) ---
    float* outb = out + ((size_t)b * NN + i0) * FOUT;
    #pragma unroll
    for (int mt = 0; mt < 2; mt++) {
        const int r0 = wm * 32 + mt * 16 + (lane >> 2);
        const int r1 = r0 + 8;
        const float inv0 = 1.0f / l_s[r0];
        const float inv1 = 1.0f / l_s[r1];
        #pragma unroll
        for (int np = 0; np < 4; np++) {
            int c = wn * 64 + np * 16 + (lane & 3) * 2;
            *(float2*)&outb[(size_t)r0 * FOUT + c]     = make_float2(acc[mt][np][0] * inv0, acc[mt][np][1] * inv0);
            *(float2*)&outb[(size_t)r1 * FOUT + c]     = make_float2(acc[mt][np][2] * inv1, acc[mt][np][3] * inv1);
            *(float2*)&outb[(size_t)r0 * FOUT + c + 8] = make_float2(acc[mt][np][4] * inv0, acc[mt][np][5] * inv0);
            *(float2*)&outb[(size_t)r1 * FOUT + c + 8] = make_float2(acc[mt][np][6] * inv1, acc[mt][np][7] * inv1);
        }
    }
}

// ---------------------------------------------------------------------------
extern "C" void kernel_launch(void* const* d_in, const int* in_sizes, int n_in,
                              void* d_out, int out_size) {
    (void)in_sizes; (void)n_in; (void)out_size;
    const float* h   = (const float*)d_in[0];
    const int*   adj = (const int*)d_in[1];
    const float* W   = (const float*)d_in[2];
    const float* a   = (const float*)d_in[3];
    float* out = (float*)d_out;

    cudaFuncSetAttribute(attn_mma_kernel,
                         cudaFuncAttributeMaxDynamicSharedMemorySize, ATTN_SMEM);

    dim3 g1(FOUT / 64, (BATCH * NN) / 64);       // (4, 256)
    gemm_wh_kernel<<<g1, 256>>>(h, W);

    dim3 gt(NN / 64, FOUT / 64, BATCH);          // (32, 4, 8)
    transp_kernel<<<gt, 256>>>();

    fvec_kernel<<<(BATCH * NN * 32) / 256, 256>>>(a);  // one warp per row

    dim3 g3(NN / BI, BATCH);                     // (32, 8)
    attn_mma_kernel<<<g3, 256, ATTN_SMEM>>>(adj, out);
}

// round 13
// speedup vs baseline: 2.1034x; 1.1483x over previous
#include <cuda_runtime.h>
#include <cuda_bf16.h>
#include <math.h>
#include <stdint.h>

#define BATCH 8
#define NN    2048
#define FIN   256
#define FOUT  256
#define NEG_INF_F (-9000000000000000.0f)
#define ALPHA_F 0.2f

#define BI 64             // i-rows per attention block
#define BJ 32             // j-cols per tile (MMA K per tile; 2 x k=16 chunks)
#define NT (NN / BJ)      // 64 tiles
#define KPAD 40           // padded k-stride (elements) for smem tiles (80 B, 16B-mult)

// Scratch (static device globals; no allocation anywhere)
__device__ __align__(16) float g_Wh[BATCH * NN * FOUT];            // 16.8 MB
__device__ __align__(16) __nv_bfloat16 g_WhhT[BATCH * FOUT * NN];  // [b][n][j] hi
__device__ __align__(16) __nv_bfloat16 g_WhlT[BATCH * FOUT * NN];  // [b][n][j] lo
__device__ float g_f1[BATCH * NN];
__device__ float g_f2[BATCH * NN];

// ---------------------------------------------------------------------------
// Helpers: ldmatrix + mma.sync + cp.async (sm_80-class PTX; valid at compute_103)
// ---------------------------------------------------------------------------
__device__ __forceinline__ uint32_t smem_u32(const void* p) {
    uint32_t a;
    asm("{ .reg .u64 t; cvta.to.shared.u64 t, %1; cvt.u32.u64 %0, t; }" : "=r"(a) : "l"(p));
    return a;
}
__device__ __forceinline__ void ldsm4(uint32_t& r0, uint32_t& r1, uint32_t& r2, uint32_t& r3,
                                      uint32_t addr) {
    asm volatile("ldmatrix.sync.aligned.m8n8.x4.shared.b16 {%0,%1,%2,%3}, [%4];"
                 : "=r"(r0), "=r"(r1), "=r"(r2), "=r"(r3) : "r"(addr));
}
__device__ __forceinline__ void mma16816(float* c, uint32_t a0, uint32_t a1, uint32_t a2,
                                         uint32_t a3, uint32_t b0, uint32_t b1) {
    asm volatile(
        "mma.sync.aligned.m16n8k16.row.col.f32.bf16.bf16.f32 "
        "{%0,%1,%2,%3}, {%4,%5,%6,%7}, {%8,%9}, {%0,%1,%2,%3};"
        : "+f"(c[0]), "+f"(c[1]), "+f"(c[2]), "+f"(c[3])
        : "r"(a0), "r"(a1), "r"(a2), "r"(a3), "r"(b0), "r"(b1));
}
#define CP_ASYNC16(dst, src) \
    asm volatile("cp.async.cg.shared.global [%0], [%1], 16;" :: "r"(dst), "l"(src))
#define CP_COMMIT() asm volatile("cp.async.commit_group;" ::: "memory")
#define CP_WAIT0()  asm volatile("cp.async.wait_group 0;" ::: "memory")

// ---------------------------------------------------------------------------
// Kernel 1: Wh[row][o] = sum_f h[row][f] * W[o][f]  (unchanged; 68.7us, passes)
// ---------------------------------------------------------------------------
__global__ void __launch_bounds__(256) gemm_wh_kernel(const float* __restrict__ h,
                                                      const float* __restrict__ W) {
    __shared__ float hs[64][33];
    __shared__ float ws[64][33];

    const int row0 = blockIdx.y * 64;
    const int col0 = blockIdx.x * 64;
    const int tid = threadIdx.x;
    const int tx = tid & 15;
    const int ty = tid >> 4;

    float acc[4][4] = {};

    for (int k0 = 0; k0 < FIN; k0 += 32) {
        #pragma unroll
        for (int t = 0; t < 8; t++) {
            int idx = tid + t * 256;
            int r = idx >> 5, k = idx & 31;
            hs[r][k] = h[(size_t)(row0 + r) * FIN + k0 + k];
            ws[r][k] = W[(size_t)(col0 + r) * FIN + k0 + k];
        }
        __syncthreads();
        #pragma unroll
        for (int k = 0; k < 32; k++) {
            float av[4], bv[4];
            #pragma unroll
            for (int i = 0; i < 4; i++) av[i] = hs[ty * 4 + i][k];
            #pragma unroll
            for (int j = 0; j < 4; j++) bv[j] = ws[tx * 4 + j][k];
            #pragma unroll
            for (int i = 0; i < 4; i++)
                #pragma unroll
                for (int j = 0; j < 4; j++)
                    acc[i][j] = fmaf(av[i], bv[j], acc[i][j]);
        }
        __syncthreads();
    }

    #pragma unroll
    for (int i = 0; i < 4; i++) {
        float4 v = make_float4(acc[i][0], acc[i][1], acc[i][2], acc[i][3]);
        *(float4*)&g_Wh[(size_t)(row0 + ty * 4 + i) * FOUT + col0 + tx * 4] = v;
    }
}

// ---------------------------------------------------------------------------
// Kernel 1b: transpose + bf16 hi/lo split: g_Wh[b][j][n] -> g_WhhT/g_WhlT[b][n][j]
// ---------------------------------------------------------------------------
__global__ void __launch_bounds__(256) transp_kernel() {
    __shared__ float ts[64][65];
    const int b  = blockIdx.z;
    const int j0 = blockIdx.x * 64;
    const int n0 = blockIdx.y * 64;
    const int tid = threadIdx.x;

    #pragma unroll
    for (int it = 0; it < 16; it++) {
        int idx = tid + it * 256;
        int r = idx >> 6, c = idx & 63;
        ts[r][c] = g_Wh[((size_t)b * NN + j0 + r) * FOUT + n0 + c];
    }
    __syncthreads();

    const int tx = tid & 31;   // j-pair index (32 pairs of j)
    const int ty = tid >> 5;   // n base (8 per iter)
    #pragma unroll
    for (int it = 0; it < 8; it++) {
        int n = ty + it * 8;
        float w0 = ts[tx * 2 + 0][n];
        float w1 = ts[tx * 2 + 1][n];
        __nv_bfloat16 h0 = __float2bfloat16(w0);
        __nv_bfloat16 h1 = __float2bfloat16(w1);
        __nv_bfloat16 l0 = __float2bfloat16(w0 - __bfloat162float(h0));
        __nv_bfloat16 l1 = __float2bfloat16(w1 - __bfloat162float(h1));
        size_t off = ((size_t)b * FOUT + n0 + n) * NN + j0 + tx * 2;
        __nv_bfloat162 vh; vh.x = h0; vh.y = h1;
        __nv_bfloat162 vl; vl.x = l0; vl.y = l1;
        *(__nv_bfloat162*)&g_WhhT[off] = vh;
        *(__nv_bfloat162*)&g_WhlT[off] = vl;
    }
}

// ---------------------------------------------------------------------------
// Kernel 2: f1/f2 (unchanged)
// ---------------------------------------------------------------------------
__global__ void __launch_bounds__(256) fvec_kernel(const float* __restrict__ a) {
    int gwarp = (blockIdx.x * blockDim.x + threadIdx.x) >> 5;
    int lane = threadIdx.x & 31;
    if (gwarp >= BATCH * NN) return;
    const float* wh = g_Wh + (size_t)gwarp * FOUT;
    float s1 = 0.f, s2 = 0.f;
    #pragma unroll
    for (int k = lane; k < FOUT; k += 32) {
        float v = wh[k];
        s1 = fmaf(v, a[k], s1);
        s2 = fmaf(v, a[FOUT + k], s2);
    }
    #pragma unroll
    for (int o = 16; o > 0; o >>= 1) {
        s1 += __shfl_xor_sync(0xffffffffu, s1, o);
        s2 += __shfl_xor_sync(0xffffffffu, s2, o);
    }
    if (lane == 0) { g_f1[gwarp] = s1; g_f2[gwarp] = s2; }
}

// ---------------------------------------------------------------------------
// Kernel 3: warp-MMA fused attention, cp.async double-buffered pipeline.
// 8 warps as 2(M) x 4(N); warp tile 32x64. ONE __syncthreads per tile:
// B(t+1) arrives via cp.async into the opposite buffer while MMA(t) runs;
// P is double-buffered so its STS never collides with in-flight MMA reads.
// 3-term split MMA: Ah*Bh + Ah*Bl + Al*Bh; unnormalized accumulate
// (|e| <= ~6 so exp can't overflow), divide by l at the end. 2 CTAs/SM.
//
// smem (102656 B dynamic), per buffer q in {0,1}:
//   B_HI(q) = q*40960          (256 x KPAD bf16 = 20480)
//   B_LO(q) = q*40960 + 20480
//   P_HI(q) = 81920 + q*10240  (64 x KPAD bf16 = 5120)
//   P_LO(q) = P_HI(q) + 5120
//   LS      = 102400           (64 f)
// ---------------------------------------------------------------------------
#define B_HI(q) ((uint32_t)(q) * 40960u)
#define B_LO(q) ((uint32_t)(q) * 40960u + 20480u)
#define P_HI(q) (81920u + (uint32_t)(q) * 10240u)
#define P_LO(q) (81920u + (uint32_t)(q) * 10240u + 5120u)
#define LS      102400u
#define ATTN_SMEM 102656

__global__ void __launch_bounds__(256, 2) attn_mma_kernel(const int* __restrict__ adj,
                                                          float* __restrict__ out) {
    extern __shared__ char smem[];
    const uint32_t sbase = smem_u32(smem);

    const int tid  = threadIdx.x;
    const int warp = tid >> 5;
    const int lane = tid & 31;
    const int b  = blockIdx.y;
    const int i0 = blockIdx.x * BI;

    const int wm = warp & 1;   // M block (32 rows)
    const int wn = warp >> 1;  // N block (64 cols)

    // softmax mapping: 4 threads per row, 8 j each
    const int sr = tid >> 2;
    const int sc = tid & 3;
    const float fi = g_f1[(size_t)b * NN + i0 + sr];
    const int* arow = adj + (size_t)b * NN * NN + (size_t)(i0 + sr) * NN + sc * 8;

    int4 pa0 = *(const int4*)(arow);
    int4 pa1 = *(const int4*)(arow + 4);

    // acc[mt][np][8]
    float acc[2][4][8];
    #pragma unroll
    for (int i = 0; i < 2; i++)
        #pragma unroll
        for (int j = 0; j < 4; j++)
            #pragma unroll
            for (int k = 0; k < 8; k++) acc[i][j][k] = 0.f;

    float lpart = 0.f;

    // per-thread cp.async source/dest for B rows (row n = tid)
    const char* srcH = (const char*)(g_WhhT + ((size_t)(b * FOUT + tid)) * NN);
    const char* srcL = (const char*)(g_WhlT + ((size_t)(b * FOUT + tid)) * NN);
    const uint32_t dRow = (uint32_t)tid * (2 * KPAD);   // 80 B/row

    // A (P) ldsm offset within a P buffer
    const uint32_t aOff = 2u * (uint32_t)((wm * 32 + (lane & 15)) * KPAD + ((lane >> 4) << 3));
    // P store offset within a P buffer
    const uint32_t pOff = (uint32_t)(sr * (2 * KPAD) + sc * 16);

    // ---- prologue: start B(0) into buffer 0 ----
    #pragma unroll
    for (int k = 0; k < 4; k++) {
        CP_ASYNC16(sbase + B_HI(0) + dRow + k * 16, srcH + k * 16);
        CP_ASYNC16(sbase + B_LO(0) + dRow + k * 16, srcL + k * 16);
    }
    CP_COMMIT();

    for (int t = 0; t < NT; t++) {
        const int j0 = t * BJ;
        const uint32_t q = (uint32_t)(t & 1);

        // --- P tile: e -> exp -> bf16 hi/lo split into Pbuf[q] ---
        {
            float4 f2a = *(const float4*)(g_f2 + (size_t)b * NN + j0 + sc * 8);
            float4 f2b = *(const float4*)(g_f2 + (size_t)b * NN + j0 + sc * 8 + 4);
            float f2v[8] = {f2a.x, f2a.y, f2a.z, f2a.w, f2b.x, f2b.y, f2b.z, f2b.w};
            int   am[8]  = {pa0.x, pa0.y, pa0.z, pa0.w, pa1.x, pa1.y, pa1.z, pa1.w};
            float pv[8];
            #pragma unroll
            for (int qq = 0; qq < 8; qq++) {
                float e = fi + f2v[qq];
                e = (e > 0.f) ? e : ALPHA_F * e;
                e = (am[qq] == 0) ? NEG_INF_F : e;
                float p = __expf(e);       // 0 when masked; |e|<=~6 otherwise
                lpart += p;
                pv[qq] = p;
            }
            union { __nv_bfloat162 h2[4]; uint4 u; } ph, pl;
            #pragma unroll
            for (int qq = 0; qq < 4; qq++) {
                __nv_bfloat16 h0 = __float2bfloat16(pv[2 * qq]);
                __nv_bfloat16 h1 = __float2bfloat16(pv[2 * qq + 1]);
                ph.h2[qq].x = h0; ph.h2[qq].y = h1;
                pl.h2[qq].x = __float2bfloat16(pv[2 * qq] - __bfloat162float(h0));
                pl.h2[qq].y = __float2bfloat16(pv[2 * qq + 1] - __bfloat162float(h1));
            }
            *(uint4*)(smem + P_HI(q) + pOff) = ph.u;
            *(uint4*)(smem + P_LO(q) + pOff) = pl.u;
        }

        // prefetch adj(t+1) into regs (latency hidden by MMA phase)
        if (t + 1 < NT) {
            pa0 = *(const int4*)(arow + (j0 + BJ));
            pa1 = *(const int4*)(arow + (j0 + BJ) + 4);
        }

        CP_WAIT0();          // own B(t) copies landed
        __syncthreads();     // all P/B(t) visible; all MMA(t-1) done

        // --- start B(t+1) into the opposite buffer (overlaps MMA below) ---
        if (t + 1 < NT) {
            const char* sH = srcH + (size_t)(j0 + BJ) * 2;
            const char* sL = srcL + (size_t)(j0 + BJ) * 2;
            const uint32_t bb = sbase + B_HI(q ^ 1) + dRow;
            const uint32_t lb = sbase + B_LO(q ^ 1) + dRow;
            #pragma unroll
            for (int k = 0; k < 4; k++) {
                CP_ASYNC16(bb + k * 16, sH + k * 16);
                CP_ASYNC16(lb + k * 16, sL + k * 16);
            }
            CP_COMMIT();
        }

        // --- MMA phase on buffers q ---
        const uint32_t aAhiBase = sbase + P_HI(q) + aOff;
        const uint32_t aAloBase = sbase + P_LO(q) + aOff;
        #pragma unroll
        for (int kc = 0; kc < 2; kc++) {
            uint32_t ah[2][4], al[2][4];
            #pragma unroll
            for (int mt = 0; mt < 2; mt++) {
                ldsm4(ah[mt][0], ah[mt][1], ah[mt][2], ah[mt][3],
                      aAhiBase + (uint32_t)(mt * 16 * KPAD * 2 + kc * 32));
                ldsm4(al[mt][0], al[mt][1], al[mt][2], al[mt][3],
                      aAloBase + (uint32_t)(mt * 16 * KPAD * 2 + kc * 32));
            }

            const int nbase = wn * 64 + (lane & 7) + ((lane >> 4) << 3);
            const int kcol  = kc * 16 + (((lane >> 3) & 1) << 3);
            #pragma unroll
            for (int np = 0; np < 4; np++) {
                uint32_t boff = 2u * (uint32_t)((nbase + np * 16) * KPAD + kcol);
                uint32_t bh0, bh1, bh2, bh3, bl0, bl1, bl2, bl3;
                ldsm4(bh0, bh1, bh2, bh3, sbase + B_HI(q) + boff);
                ldsm4(bl0, bl1, bl2, bl3, sbase + B_LO(q) + boff);
                #pragma unroll
                for (int mt = 0; mt < 2; mt++) {
                    mma16816(acc[mt][np] + 0, ah[mt][0], ah[mt][1], ah[mt][2], ah[mt][3], bh0, bh1);
                    mma16816(acc[mt][np] + 0, ah[mt][0], ah[mt][1], ah[mt][2], ah[mt][3], bl0, bl1);
                    mma16816(acc[mt][np] + 0, al[mt][0], al[mt][1], al[mt][2], al[mt][3], bh0, bh1);
                    mma16816(acc[mt][np] + 4, ah[mt][0], ah[mt][1], ah[mt][2], ah[mt][3], bh2, bh3);
                    mma16816(acc[mt][np] + 4, ah[mt][0], ah[mt][1], ah[mt][2], ah[mt][3], bl2, bl3);
                    mma16816(acc[mt][np] + 4, al[mt][0], al[mt][1], al[mt][2], al[mt][3], bh2, bh3);
                }
            }
        }
    }

    // --- l reduction across the 4-thread row group (consecutive lanes) ---
    float ls = lpart;
    ls += __shfl_xor_sync(0xffffffffu, ls, 1);
    ls += __shfl_xor_sync(0xffffffffu, ls, 2);
    float* l_s = (float*)(smem + LS);
    __syncthreads();             // last tile's MMA done before LS write aliasing (distinct region, but keep order clean)
    if (sc == 0) l_s[sr] = ls;
    __syncthreads();

    // --- normalize + write (fp32, 8B stores; 32B contiguous per 4 lanes) ---
    float* outb = out + ((size_t)b * NN + i0) * FOUT;
    #pragma unroll
    for (int mt = 0; mt < 2; mt++) {
        const int r0 = wm * 32 + mt * 16 + (lane >> 2);
        const int r1 = r0 + 8;
        const float inv0 = 1.0f / l_s[r0];
        const float inv1 = 1.0f / l_s[r1];
        #pragma unroll
        for (int np = 0; np < 4; np++) {
            int c = wn * 64 + np * 16 + (lane & 3) * 2;
            *(float2*)&outb[(size_t)r0 * FOUT + c]     = make_float2(acc[mt][np][0] * inv0, acc[mt][np][1] * inv0);
            *(float2*)&outb[(size_t)r1 * FOUT + c]     = make_float2(acc[mt][np][2] * inv1, acc[mt][np][3] * inv1);
            *(float2*)&outb[(size_t)r0 * FOUT + c + 8] = make_float2(acc[mt][np][4] * inv0, acc[mt][np][5] * inv0);
            *(float2*)&outb[(size_t)r1 * FOUT + c + 8] = make_float2(acc[mt][np][6] * inv1, acc[mt][np][7] * inv1);
        }
    }
}

// ---------------------------------------------------------------------------
extern "C" void kernel_launch(void* const* d_in, const int* in_sizes, int n_in,
                              void* d_out, int out_size) {
    (void)in_sizes; (void)n_in; (void)out_size;
    const float* h   = (const float*)d_in[0];
    const int*   adj = (const int*)d_in[1];
    const float* W   = (const float*)d_in[2];
    const float* a   = (const float*)d_in[3];
    float* out = (float*)d_out;

    cudaFuncSetAttribute(attn_mma_kernel,
                         cudaFuncAttributeMaxDynamicSharedMemorySize, ATTN_SMEM);

    dim3 g1(FOUT / 64, (BATCH * NN) / 64);       // (4, 256)
    gemm_wh_kernel<<<g1, 256>>>(h, W);

    dim3 gt(NN / 64, FOUT / 64, BATCH);          // (32, 4, 8)
    transp_kernel<<<gt, 256>>>();

    fvec_kernel<<<(BATCH * NN * 32) / 256, 256>>>(a);  // one warp per row

    dim3 g3(NN / BI, BATCH);                     // (32, 8)
    attn_mma_kernel<<<g3, 256, ATTN_SMEM>>>(adj, out);
}

// round 15
// speedup vs baseline: 3.1697x; 1.5069x over previous
#include <cuda_runtime.h>
#include <cuda_fp16.h>
#include <math.h>
#include <stdint.h>

#define BATCH 8
#define NN    2048
#define FIN   256
#define FOUT  256
#define NEG_INF_F (-9000000000000000.0f)
#define ALPHA_F 0.2f

#define BI 64             // i-rows per attention block
#define BJ 32             // j-cols per tile (MMA K per tile; 2 x k=16 chunks)
#define NT (NN / BJ)      // 64 tiles
#define KPAD 40           // padded k-stride (elements) for smem tiles (80 B, 16B-mult)

// Scratch (static device globals; no allocation anywhere)
__device__ __align__(16) float g_Wh[BATCH * NN * FOUT];        // 16.8 MB
__device__ __align__(16) __half g_WhT[BATCH * FOUT * NN];      // [b][n][j] fp16
__device__ float g_f1[BATCH * NN];
__device__ float g_f2[BATCH * NN];

// ---------------------------------------------------------------------------
// Helpers: ldmatrix + mma.sync + cp.async (sm_80-class PTX; valid at compute_103)
// ---------------------------------------------------------------------------
__device__ __forceinline__ uint32_t smem_u32(const void* p) {
    uint32_t a;
    asm("{ .reg .u64 t; cvta.to.shared.u64 t, %1; cvt.u32.u64 %0, t; }" : "=r"(a) : "l"(p));
    return a;
}
__device__ __forceinline__ void ldsm4(uint32_t& r0, uint32_t& r1, uint32_t& r2, uint32_t& r3,
                                      uint32_t addr) {
    asm volatile("ldmatrix.sync.aligned.m8n8.x4.shared.b16 {%0,%1,%2,%3}, [%4];"
                 : "=r"(r0), "=r"(r1), "=r"(r2), "=r"(r3) : "r"(addr));
}
__device__ __forceinline__ void mma16816h(float* c, uint32_t a0, uint32_t a1, uint32_t a2,
                                          uint32_t a3, uint32_t b0, uint32_t b1) {
    asm volatile(
        "mma.sync.aligned.m16n8k16.row.col.f32.f16.f16.f32 "
        "{%0,%1,%2,%3}, {%4,%5,%6,%7}, {%8,%9}, {%0,%1,%2,%3};"
        : "+f"(c[0]), "+f"(c[1]), "+f"(c[2]), "+f"(c[3])
        : "r"(a0), "r"(a1), "r"(a2), "r"(a3), "r"(b0), "r"(b1));
}
#define CP_ASYNC16(dst, src) \
    asm volatile("cp.async.cg.shared.global [%0], [%1], 16;" :: "r"(dst), "l"(src))
#define CP_COMMIT() asm volatile("cp.async.commit_group;" ::: "memory")
#define CP_WAIT0()  asm volatile("cp.async.wait_group 0;" ::: "memory")

// ---------------------------------------------------------------------------
// Kernel 1: Wh[row][o] = sum_f h[row][f] * W[o][f]  (unchanged; 68.7us, passes)
// ---------------------------------------------------------------------------
__global__ void __launch_bounds__(256) gemm_wh_kernel(const float* __restrict__ h,
                                                      const float* __restrict__ W) {
    __shared__ float hs[64][33];
    __shared__ float ws[64][33];

    const int row0 = blockIdx.y * 64;
    const int col0 = blockIdx.x * 64;
    const int tid = threadIdx.x;
    const int tx = tid & 15;
    const int ty = tid >> 4;

    float acc[4][4] = {};

    for (int k0 = 0; k0 < FIN; k0 += 32) {
        #pragma unroll
        for (int t = 0; t < 8; t++) {
            int idx = tid + t * 256;
            int r = idx >> 5, k = idx & 31;
            hs[r][k] = h[(size_t)(row0 + r) * FIN + k0 + k];
            ws[r][k] = W[(size_t)(col0 + r) * FIN + k0 + k];
        }
        __syncthreads();
        #pragma unroll
        for (int k = 0; k < 32; k++) {
            float av[4], bv[4];
            #pragma unroll
            for (int i = 0; i < 4; i++) av[i] = hs[ty * 4 + i][k];
            #pragma unroll
            for (int j = 0; j < 4; j++) bv[j] = ws[tx * 4 + j][k];
            #pragma unroll
            for (int i = 0; i < 4; i++)
                #pragma unroll
                for (int j = 0; j < 4; j++)
                    acc[i][j] = fmaf(av[i], bv[j], acc[i][j]);
        }
        __syncthreads();
    }

    #pragma unroll
    for (int i = 0; i < 4; i++) {
        float4 v = make_float4(acc[i][0], acc[i][1], acc[i][2], acc[i][3]);
        *(float4*)&g_Wh[(size_t)(row0 + ty * 4 + i) * FOUT + col0 + tx * 4] = v;
    }
}

// ---------------------------------------------------------------------------
// Kernel 1b: transpose + fp16 convert: g_Wh[b][j][n] -> g_WhT[b][n][j]
// ---------------------------------------------------------------------------
__global__ void __launch_bounds__(256) transp_kernel() {
    __shared__ float ts[64][65];
    const int b  = blockIdx.z;
    const int j0 = blockIdx.x * 64;
    const int n0 = blockIdx.y * 64;
    const int tid = threadIdx.x;

    #pragma unroll
    for (int it = 0; it < 16; it++) {
        int idx = tid + it * 256;
        int r = idx >> 6, c = idx & 63;
        ts[r][c] = g_Wh[((size_t)b * NN + j0 + r) * FOUT + n0 + c];
    }
    __syncthreads();

    const int tx = tid & 31;   // j-pair index (32 pairs of j)
    const int ty = tid >> 5;   // n base (8 per iter)
    #pragma unroll
    for (int it = 0; it < 8; it++) {
        int n = ty + it * 8;
        float w0 = ts[tx * 2 + 0][n];
        float w1 = ts[tx * 2 + 1][n];
        size_t off = ((size_t)b * FOUT + n0 + n) * NN + j0 + tx * 2;
        __half2 v; v.x = __float2half(w0); v.y = __float2half(w1);
        *(__half2*)&g_WhT[off] = v;
    }
}

// ---------------------------------------------------------------------------
// Kernel 2: f1/f2 (unchanged)
// ---------------------------------------------------------------------------
__global__ void __launch_bounds__(256) fvec_kernel(const float* __restrict__ a) {
    int gwarp = (blockIdx.x * blockDim.x + threadIdx.x) >> 5;
    int lane = threadIdx.x & 31;
    if (gwarp >= BATCH * NN) return;
    const float* wh = g_Wh + (size_t)gwarp * FOUT;
    float s1 = 0.f, s2 = 0.f;
    #pragma unroll
    for (int k = lane; k < FOUT; k += 32) {
        float v = wh[k];
        s1 = fmaf(v, a[k], s1);
        s2 = fmaf(v, a[FOUT + k], s2);
    }
    #pragma unroll
    for (int o = 16; o > 0; o >>= 1) {
        s1 += __shfl_xor_sync(0xffffffffu, s1, o);
        s2 += __shfl_xor_sync(0xffffffffu, s2, o);
    }
    if (lane == 0) { g_f1[gwarp] = s1; g_f2[gwarp] = s2; }
}

// ---------------------------------------------------------------------------
// Kernel 3: warp-MMA fused attention, fp16 single-term, cp.async pipeline.
// 8 warps as 2(M) x 4(N); warp tile 32x64. ONE __syncthreads per tile.
// fp16 m16n8k16 (fp32 acc): 32 mma + 12 ldsm per warp-tile (was 96 + 24).
// Unnormalized accumulate (|e| <= ~7 -> P <= ~1100, no fp16 overflow);
// divide by fp32 l at the end. 2 CTAs/SM.
//
// smem (51456 B dynamic), buffer q in {0,1}:
//   B(q) = q*20480         (256 x KPAD fp16 = 20480)
//   P(q) = 40960 + q*5120  (64 x KPAD fp16 = 5120)
//   LS   = 51200           (64 f)
// ---------------------------------------------------------------------------
#define B_BUF(q) ((uint32_t)(q) * 20480u)
#define P_BUF(q) (40960u + (uint32_t)(q) * 5120u)
#define LS       51200u
#define ATTN_SMEM 51456

__global__ void __launch_bounds__(256, 2) attn_mma_kernel(const int* __restrict__ adj,
                                                          float* __restrict__ out) {
    extern __shared__ char smem[];
    const uint32_t sbase = smem_u32(smem);

    const int tid  = threadIdx.x;
    const int warp = tid >> 5;
    const int lane = tid & 31;
    const int b  = blockIdx.y;
    const int i0 = blockIdx.x * BI;

    const int wm = warp & 1;   // M block (32 rows)
    const int wn = warp >> 1;  // N block (64 cols)

    // softmax mapping: 4 threads per row, 8 j each
    const int sr = tid >> 2;
    const int sc = tid & 3;
    const float fi = g_f1[(size_t)b * NN + i0 + sr];
    const int* arow = adj + (size_t)b * NN * NN + (size_t)(i0 + sr) * NN + sc * 8;

    int4 pa0 = *(const int4*)(arow);
    int4 pa1 = *(const int4*)(arow + 4);

    // acc[mt][np][8]
    float acc[2][4][8];
    #pragma unroll
    for (int i = 0; i < 2; i++)
        #pragma unroll
        for (int j = 0; j < 4; j++)
            #pragma unroll
            for (int k = 0; k < 8; k++) acc[i][j][k] = 0.f;

    float lpart = 0.f;

    // per-thread cp.async source/dest for B rows (row n = tid)
    const char* srcB = (const char*)(g_WhT + ((size_t)(b * FOUT + tid)) * NN);
    const uint32_t dRow = (uint32_t)tid * (2 * KPAD);   // 80 B/row

    // A (P) ldsm offset within a P buffer
    const uint32_t aOff = 2u * (uint32_t)((wm * 32 + (lane & 15)) * KPAD + ((lane >> 4) << 3));
    // P store offset within a P buffer
    const uint32_t pOff = (uint32_t)(sr * (2 * KPAD) + sc * 16);

    // ---- prologue: start B(0) into buffer 0 ----
    #pragma unroll
    for (int k = 0; k < 4; k++)
        CP_ASYNC16(sbase + B_BUF(0) + dRow + k * 16, srcB + k * 16);
    CP_COMMIT();

    for (int t = 0; t < NT; t++) {
        const int j0 = t * BJ;
        const uint32_t q = (uint32_t)(t & 1);

        // --- P tile: e -> exp -> fp16 into Pbuf[q] ---
        {
            float4 f2a = *(const float4*)(g_f2 + (size_t)b * NN + j0 + sc * 8);
            float4 f2b = *(const float4*)(g_f2 + (size_t)b * NN + j0 + sc * 8 + 4);
            float f2v[8] = {f2a.x, f2a.y, f2a.z, f2a.w, f2b.x, f2b.y, f2b.z, f2b.w};
            int   am[8]  = {pa0.x, pa0.y, pa0.z, pa0.w, pa1.x, pa1.y, pa1.z, pa1.w};
            union { __half2 h2[4]; uint4 u; } ph;
            #pragma unroll
            for (int qq = 0; qq < 4; qq++) {
                float e0 = fi + f2v[2 * qq];
                float e1 = fi + f2v[2 * qq + 1];
                e0 = (e0 > 0.f) ? e0 : ALPHA_F * e0;
                e1 = (e1 > 0.f) ? e1 : ALPHA_F * e1;
                e0 = (am[2 * qq] == 0)     ? NEG_INF_F : e0;
                e1 = (am[2 * qq + 1] == 0) ? NEG_INF_F : e1;
                float p0 = __expf(e0);     // 0 when masked; |e|<=~7 otherwise
                float p1 = __expf(e1);
                lpart += p0 + p1;
                ph.h2[qq].x = __float2half(p0);
                ph.h2[qq].y = __float2half(p1);
            }
            *(uint4*)(smem + P_BUF(q) + pOff) = ph.u;
        }

        // prefetch adj(t+1) into regs (latency hidden by MMA phase)
        if (t + 1 < NT) {
            pa0 = *(const int4*)(arow + (j0 + BJ));
            pa1 = *(const int4*)(arow + (j0 + BJ) + 4);
        }

        CP_WAIT0();          // own B(t) copies landed
        __syncthreads();     // all P/B(t) visible; all MMA(t-1) done

        // --- start B(t+1) into the opposite buffer (overlaps MMA below) ---
        if (t + 1 < NT) {
            const char* sB = srcB + (size_t)(j0 + BJ) * 2;
            const uint32_t bb = sbase + B_BUF(q ^ 1) + dRow;
            #pragma unroll
            for (int k = 0; k < 4; k++)
                CP_ASYNC16(bb + k * 16, sB + k * 16);
            CP_COMMIT();
        }

        // --- MMA phase on buffers q: 2 kc x (2 A-ldsm + 4 B-ldsm + 16 mma) ---
        const uint32_t aABase = sbase + P_BUF(q) + aOff;
        #pragma unroll
        for (int kc = 0; kc < 2; kc++) {
            uint32_t ah[2][4];
            #pragma unroll
            for (int mt = 0; mt < 2; mt++)
                ldsm4(ah[mt][0], ah[mt][1], ah[mt][2], ah[mt][3],
                      aABase + (uint32_t)(mt * 16 * KPAD * 2 + kc * 32));

            const int nbase = wn * 64 + (lane & 7) + ((lane >> 4) << 3);
            const int kcol  = kc * 16 + (((lane >> 3) & 1) << 3);
            #pragma unroll
            for (int np = 0; np < 4; np++) {
                uint32_t boff = 2u * (uint32_t)((nbase + np * 16) * KPAD + kcol);
                uint32_t b0, b1, b2, b3;
                ldsm4(b0, b1, b2, b3, sbase + B_BUF(q) + boff);
                #pragma unroll
                for (int mt = 0; mt < 2; mt++) {
                    mma16816h(acc[mt][np] + 0, ah[mt][0], ah[mt][1], ah[mt][2], ah[mt][3], b0, b1);
                    mma16816h(acc[mt][np] + 4, ah[mt][0], ah[mt][1], ah[mt][2], ah[mt][3], b2, b3);
                }
            }
        }
    }

    // --- l reduction across the 4-thread row group (consecutive lanes) ---
    float ls = lpart;
    ls += __shfl_xor_sync(0xffffffffu, ls, 1);
    ls += __shfl_xor_sync(0xffffffffu, ls, 2);
    float* l_s = (float*)(smem + LS);
    __syncthreads();
    if (sc == 0) l_s[sr] = ls;
    __syncthreads();

    // --- normalize + write (fp32, 8B stores; 32B contiguous per 4 lanes) ---
    float* outb = out + ((size_t)b * NN + i0) * FOUT;
    #pragma unroll
    for (int mt = 0; mt < 2; mt++) {
        const int r0 = wm * 32 + mt * 16 + (lane >> 2);
        const int r1 = r0 + 8;
        const float inv0 = 1.0f / l_s[r0];
        const float inv1 = 1.0f / l_s[r1];
        #pragma unroll
        for (int np = 0; np < 4; np++) {
            int c = wn * 64 + np * 16 + (lane & 3) * 2;
            *(float2*)&outb[(size_t)r0 * FOUT + c]     = make_float2(acc[mt][np][0] * inv0, acc[mt][np][1] * inv0);
            *(float2*)&outb[(size_t)r1 * FOUT + c]     = make_float2(acc[mt][np][2] * inv1, acc[mt][np][3] * inv1);
            *(float2*)&outb[(size_t)r0 * FOUT + c + 8] = make_float2(acc[mt][np][4] * inv0, acc[mt][np][5] * inv0);
            *(float2*)&outb[(size_t)r1 * FOUT + c + 8] = make_float2(acc[mt][np][6] * inv1, acc[mt][np][7] * inv1);
        }
    }
}

// ---------------------------------------------------------------------------
extern "C" void kernel_launch(void* const* d_in, const int* in_sizes, int n_in,
                              void* d_out, int out_size) {
    (void)in_sizes; (void)n_in; (void)out_size;
    const float* h   = (const float*)d_in[0];
    const int*   adj = (const int*)d_in[1];
    const float* W   = (const float*)d_in[2];
    const float* a   = (const float*)d_in[3];
    float* out = (float*)d_out;

    cudaFuncSetAttribute(attn_mma_kernel,
                         cudaFuncAttributeMaxDynamicSharedMemorySize, ATTN_SMEM);

    dim3 g1(FOUT / 64, (BATCH * NN) / 64);       // (4, 256)
    gemm_wh_kernel<<<g1, 256>>>(h, W);

    dim3 gt(NN / 64, FOUT / 64, BATCH);          // (32, 4, 8)
    transp_kernel<<<gt, 256>>>();

    fvec_kernel<<<(BATCH * NN * 32) / 256, 256>>>(a);  // one warp per row

    dim3 g3(NN / BI, BATCH);                     // (32, 8)
    attn_mma_kernel<<<g3, 256, ATTN_SMEM>>>(adj, out);
}